// round 1
// baseline (speedup 1.0000x reference)
#include <cuda_runtime.h>
#include <cuda_bf16.h>
#include <math.h>

// Problem constants (fixed shapes)
#define BB 128
#define NN 512
#define HH 128
#define TT 32
#define G4 512   // 4*H

// JAX threefry mode: 1 = partitionable (default since jax 0.5), 0 = legacy/original
#define JAX_PARTITIONABLE 1

// ------------------------- device scratch (static; allocation-free) -------------------------
__device__ float g_te[(size_t)BB * HH * NN];   // tanh(enc_trans) transposed: [b][k][n]  (33.5 MB)
__device__ float g_WihT[HH * G4];              // [hh][j]
__device__ float g_WhhT[HH * G4];              // [hh][j]
__device__ float g_W2T[HH * HH];               // [hh][k]
__device__ float g_W1T[HH * HH];               // [hh][k]
__device__ unsigned int g_sub[TT * 2];         // per-step categorical subkeys

// ------------------------- Threefry-2x32 (matches JAX exactly) -------------------------
__device__ __forceinline__ unsigned rotl32(unsigned x, int r) {
    return (x << r) | (x >> (32 - r));
}

__device__ __forceinline__ void tf2x32(unsigned k0, unsigned k1,
                                       unsigned x0, unsigned x1,
                                       unsigned& o0, unsigned& o1) {
    unsigned ks2 = k0 ^ k1 ^ 0x1BD11BDAu;
    x0 += k0; x1 += k1;
#define TF_RND(r) { x0 += x1; x1 = rotl32(x1, r); x1 ^= x0; }
    TF_RND(13) TF_RND(15) TF_RND(26) TF_RND(6)
    x0 += k1; x1 += ks2 + 1u;
    TF_RND(17) TF_RND(29) TF_RND(16) TF_RND(24)
    x0 += ks2; x1 += k0 + 2u;
    TF_RND(13) TF_RND(15) TF_RND(26) TF_RND(6)
    x0 += k0; x1 += k1 + 3u;
    TF_RND(17) TF_RND(29) TF_RND(16) TF_RND(24)
    x0 += k1; x1 += ks2 + 4u;
    TF_RND(13) TF_RND(15) TF_RND(26) TF_RND(6)
    x0 += ks2; x1 += k0 + 5u;
#undef TF_RND
    o0 = x0; o1 = x1;
}

// ------------------------- prep: weight transposes + subkey chain -------------------------
__global__ void k_prep(const float* __restrict__ W_ih, const float* __restrict__ W_hh,
                       const float* __restrict__ W1,   const float* __restrict__ W2) {
    int tid = blockIdx.x * blockDim.x + threadIdx.x;     // 64*256 = 16384 threads
    const int NT = 64 * 256;
    for (int i = tid; i < G4 * HH; i += NT) {
        int j = i / HH, hh = i % HH;
        g_WihT[hh * G4 + j] = W_ih[i];
        g_WhhT[hh * G4 + j] = W_hh[i];
    }
    for (int i = tid; i < HH * HH; i += NT) {
        int k = i / HH, hh = i % HH;
        g_W2T[hh * HH + k] = W2[i];
        g_W1T[hh * HH + k] = W1[i];
    }
    if (tid == 0) {
        // key = jax.random.key(42) -> (0, 42); chain: key, sub = split(key)
        unsigned k0 = 0u, k1 = 42u;
        for (int t = 0; t < TT; t++) {
#if JAX_PARTITIONABLE
            unsigned a0, a1, b0, b1;
            tf2x32(k0, k1, 0u, 0u, a0, a1);   // new key
            tf2x32(k0, k1, 0u, 1u, b0, b1);   // sub key
            g_sub[2 * t] = b0; g_sub[2 * t + 1] = b1;
            k0 = a0; k1 = a1;
#else
            // original: counts iota(4) -> pairs (0,2),(1,3); out=concat(o0s,o1s).reshape(2,2)
            unsigned p0, p1, q0, q1;
            tf2x32(k0, k1, 0u, 2u, p0, p1);
            tf2x32(k0, k1, 1u, 3u, q0, q1);
            g_sub[2 * t] = p1; g_sub[2 * t + 1] = q1;  // sub = row 1 = (o1 of pair0, o1 of pair1)
            k0 = p0; k1 = q0;                          // new key = row 0
#endif
        }
    }
}

// ------------------------- enc_trans: g_te[b][k][n] = tanh(sum_h enc[b,n,h]*W1[k,h]) ------
__global__ __launch_bounds__(128) void k_enc(const float* __restrict__ enc) {
    __shared__ float sA[32 * HH];   // enc tile [32 n][128 h]
    int b = blockIdx.y;
    int n0 = blockIdx.x * 32;
    for (int i = threadIdx.x; i < 32 * HH; i += 128)
        sA[i] = enc[((size_t)b * NN + n0) * HH + i];
    __syncthreads();

    int k = threadIdx.x;
    float acc[32];
#pragma unroll
    for (int n = 0; n < 32; n++) acc[n] = 0.f;

#pragma unroll 4
    for (int h = 0; h < HH; h++) {
        float w = g_W1T[h * HH + k];
#pragma unroll
        for (int n = 0; n < 32; n++)
            acc[n] = fmaf(sA[n * HH + h], w, acc[n]);
    }
    float* dst = g_te + ((size_t)b * HH + k) * NN + n0;
#pragma unroll
    for (int n = 0; n < 32; n++) dst[n] = tanhf(acc[n]);
}

// ------------------------- persistent per-batch decode -------------------------
__global__ __launch_bounds__(512) void k_decode(const float* __restrict__ enc,
                                                const float* __restrict__ b_ih,
                                                const float* __restrict__ b_hh,
                                                const float* __restrict__ v,
                                                float* __restrict__ out) {
    __shared__ float s_dec[HH], s_hx[HH], s_cx[HH], s_td[HH], s_v[HH];
    __shared__ float s_score[NN];
    __shared__ float s_red[NN];
    __shared__ int   s_redi[NN];
    __shared__ unsigned char s_mask[NN];
    __shared__ int   s_sel;
    __shared__ float s_smax;

    const int b = blockIdx.x;
    const int tid = threadIdx.x;
    const float NEG_INF = __int_as_float(0xff800000);

    if (tid < HH) { s_hx[tid] = 0.f; s_cx[tid] = 0.f; s_v[tid] = v[tid]; }
    s_mask[tid] = 0;

    // dec0 = mean over n of encoder_outputs[b]
    {
        int h = tid & 127, q = tid >> 7;
        const float* p = enc + ((size_t)b * NN + (size_t)q * 128) * HH + h;
        float sum = 0.f;
        for (int n = 0; n < 128; n++) sum += p[(size_t)n * HH];
        s_red[tid] = sum;
        __syncthreads();
        if (tid < HH)
            s_dec[tid] = (s_red[tid] + s_red[tid + 128] + s_red[tid + 256] + s_red[tid + 384]) * (1.0f / NN);
    }
    __syncthreads();

    const float* teb = g_te + (size_t)b * HH * NN;
    const float bias = b_ih[tid] + b_hh[tid];   // j = tid (512 gate outputs)

    for (int t = 0; t < TT; t++) {
        // --- Phase 1: gates[j] = bias + dec . WihT[:,j] + hx . WhhT[:,j] ---
        {
            float acc = bias;
#pragma unroll 4
            for (int hh = 0; hh < HH; hh++) {
                acc = fmaf(s_dec[hh], g_WihT[hh * G4 + tid], acc);
                acc = fmaf(s_hx[hh],  g_WhhT[hh * G4 + tid], acc);
            }
            s_red[tid] = acc;
        }
        __syncthreads();

        // --- Phase 2: LSTM cell update (torch gate order i,f,g,o) ---
        if (tid < HH) {
            float gi = s_red[tid];
            float gf = s_red[HH + tid];
            float gg = s_red[2 * HH + tid];
            float go = s_red[3 * HH + tid];
            float si = fmaf(0.5f, tanhf(0.5f * gi), 0.5f);   // logistic (XLA-style)
            float sf = fmaf(0.5f, tanhf(0.5f * gf), 0.5f);
            float tg = tanhf(gg);
            float so = fmaf(0.5f, tanhf(0.5f * go), 0.5f);
            float c  = fmaf(sf, s_cx[tid], si * tg);
            s_cx[tid] = c;
            s_hx[tid] = so * tanhf(c);
        }
        __syncthreads();

        // --- Phase 3: td[k] = tanh(hx . W2T[:,k]) ---
        {
            int k = tid & 127, q = tid >> 7;
            float p = 0.f;
#pragma unroll
            for (int hh = q * 32; hh < q * 32 + 32; hh++)
                p = fmaf(s_hx[hh], g_W2T[hh * HH + k], p);
            s_red[tid] = p;
        }
        __syncthreads();
        if (tid < HH)
            s_td[tid] = tanhf(s_red[tid] + s_red[tid + 128] + s_red[tid + 256] + s_red[tid + 384]);
        __syncthreads();

        // --- Phase 4: score[n] = sum_k v[k] * tanh(te + td) via tanh-addition identity ---
        {
            const int n = tid;
            const float* tp = teb + n;    // te[b][k][n], stride NN per k
            float s = 0.f;
#pragma unroll 4
            for (int k = 0; k < HH; k++) {
                float te  = tp[(size_t)k * NN];
                float td  = s_td[k];
                float num = te + td;
                float den = fmaf(te, td, 1.0f);
                s = fmaf(s_v[k], __fdividef(num, den), s);
            }

            // gumbel noise (exact JAX threefry + uniform + gumbel pipeline)
            unsigned sk0 = g_sub[2 * t], sk1 = g_sub[2 * t + 1];
            unsigned idx = (unsigned)(b * NN + n);
            unsigned bits, o0, o1;
#if JAX_PARTITIONABLE
            tf2x32(sk0, sk1, 0u, idx, o0, o1);
            bits = o0 ^ o1;
#else
            if (idx < 32768u) { tf2x32(sk0, sk1, idx, idx + 32768u, o0, o1); bits = o0; }
            else              { tf2x32(sk0, sk1, idx - 32768u, idx, o0, o1); bits = o1; }
#endif
            float f   = __uint_as_float((bits >> 9) | 0x3f800000u) - 1.0f;
            float u   = fmaxf(1.17549435e-38f, f);
            float gum = -logf(-logf(u));

            float sm = s_mask[n] ? NEG_INF : s;
            s_score[n] = sm;
            s_red[n]   = sm + gum;
            s_redi[n]  = n;
        }
        __syncthreads();

        // argmax(score + gumbel), first-index tie-break
        for (int off = 256; off > 0; off >>= 1) {
            if (tid < off) {
                float v2 = s_red[tid + off];
                float v1 = s_red[tid];
                int   i2 = s_redi[tid + off];
                if (v2 > v1 || (v2 == v1 && i2 < s_redi[tid])) {
                    s_red[tid] = v2; s_redi[tid] = i2;
                }
            }
            __syncthreads();
        }
        if (tid == 0) s_sel = s_redi[0];
        __syncthreads();

        // softmax max
        s_red[tid] = s_score[tid];
        __syncthreads();
        for (int off = 256; off > 0; off >>= 1) {
            if (tid < off) s_red[tid] = fmaxf(s_red[tid], s_red[tid + off]);
            __syncthreads();
        }
        if (tid == 0) s_smax = s_red[0];
        __syncthreads();

        // softmax denominator
        float smax = s_smax;
        s_red[tid] = expf(s_score[tid] - smax);   // exp(-inf) = 0 for masked
        __syncthreads();
        for (int off = 256; off > 0; off >>= 1) {
            if (tid < off) s_red[tid] += s_red[tid + off];
            __syncthreads();
        }

        int sel = s_sel;
        if (tid == 0) {
            float prob = expf(s_score[sel] - smax) / s_red[0];
            out[b * TT + t]           = (float)sel;
            out[BB * TT + b * TT + t] = logf(prob + 1e-9f);
            s_mask[sel] = 1;
        }
        __syncthreads();   // mask write + everyone done with s_dec before overwrite

        if (tid < HH)
            s_dec[tid] = enc[((size_t)b * NN + sel) * HH + tid];
        __syncthreads();
    }
}

// ------------------------- launcher -------------------------
extern "C" void kernel_launch(void* const* d_in, const int* in_sizes, int n_in,
                              void* d_out, int out_size) {
    const float* enc  = (const float*)d_in[0];
    const float* W_ih = (const float*)d_in[1];
    const float* W_hh = (const float*)d_in[2];
    const float* b_ih = (const float*)d_in[3];
    const float* b_hh = (const float*)d_in[4];
    const float* W1   = (const float*)d_in[5];
    const float* W2   = (const float*)d_in[6];
    const float* v    = (const float*)d_in[7];
    (void)in_sizes; (void)n_in; (void)out_size;

    k_prep<<<64, 256>>>(W_ih, W_hh, W1, W2);
    k_enc<<<dim3(16, BB), 128>>>(enc);
    k_decode<<<BB, 512>>>(enc, b_ih, b_hh, v, (float*)d_out);
}

// round 3
// speedup vs baseline: 2.2446x; 2.2446x over previous
#include <cuda_runtime.h>
#include <cuda_bf16.h>
#include <math.h>

// Problem constants (fixed shapes)
#define BB 128
#define NN 512
#define HH 128
#define TT 32
#define G4 512   // 4*H
#define SH 52    // weight hh-rows cached in smem (52*4KB = 208KB)

// ------------------------- device scratch (static; allocation-free) -------------------------
__device__ float  g_te[(size_t)BB * HH * NN];   // tanh(enc_trans): [b][k][n]  (33.5 MB)
__device__ float2 g_Wc[HH * G4];                // fused weights [hh][j] = {Wih[j][hh], Whh[j][hh]}
__device__ float  g_W2T[HH * HH];               // [hh][k]
__device__ float  g_W1T[HH * HH];               // [hh][k]
__device__ unsigned int g_sub[TT * 2];          // per-step categorical subkeys

// ------------------------- Threefry-2x32 (matches JAX partitionable mode) -------------------
__device__ __forceinline__ unsigned rotl32(unsigned x, int r) {
    return (x << r) | (x >> (32 - r));
}

__device__ __forceinline__ void tf2x32(unsigned k0, unsigned k1,
                                       unsigned x0, unsigned x1,
                                       unsigned& o0, unsigned& o1) {
    unsigned ks2 = k0 ^ k1 ^ 0x1BD11BDAu;
    x0 += k0; x1 += k1;
#define TF_RND(r) { x0 += x1; x1 = rotl32(x1, r); x1 ^= x0; }
    TF_RND(13) TF_RND(15) TF_RND(26) TF_RND(6)
    x0 += k1; x1 += ks2 + 1u;
    TF_RND(17) TF_RND(29) TF_RND(16) TF_RND(24)
    x0 += ks2; x1 += k0 + 2u;
    TF_RND(13) TF_RND(15) TF_RND(26) TF_RND(6)
    x0 += k0; x1 += k1 + 3u;
    TF_RND(17) TF_RND(29) TF_RND(16) TF_RND(24)
    x0 += k1; x1 += ks2 + 4u;
    TF_RND(13) TF_RND(15) TF_RND(26) TF_RND(6)
    x0 += ks2; x1 += k0 + 5u;
#undef TF_RND
    o0 = x0; o1 = x1;
}

// ------------------------- prep: weight layouts + subkey chain -------------------------
__global__ void k_prep(const float* __restrict__ W_ih, const float* __restrict__ W_hh,
                       const float* __restrict__ W1,   const float* __restrict__ W2) {
    int tid = blockIdx.x * blockDim.x + threadIdx.x;     // 64*256 = 16384 threads
    const int NT = 64 * 256;
    for (int i = tid; i < G4 * HH; i += NT) {
        int j = i / HH, hh = i % HH;
        g_Wc[hh * G4 + j] = make_float2(W_ih[i], W_hh[i]);
    }
    for (int i = tid; i < HH * HH; i += NT) {
        int k = i / HH, hh = i % HH;
        g_W2T[hh * HH + k] = W2[i];
        g_W1T[hh * HH + k] = W1[i];
    }
    if (tid == 0) {
        // key = jax.random.key(42) -> (0, 42); chain: key, sub = split(key)
        unsigned k0 = 0u, k1 = 42u;
        for (int t = 0; t < TT; t++) {
            unsigned a0, a1, b0, b1;
            tf2x32(k0, k1, 0u, 0u, a0, a1);   // new key
            tf2x32(k0, k1, 0u, 1u, b0, b1);   // sub key
            g_sub[2 * t] = b0; g_sub[2 * t + 1] = b1;
            k0 = a0; k1 = a1;
        }
    }
}

// ------------------------- enc_trans: g_te[b][k][n] = tanh(sum_h enc[b,n,h]*W1[k,h]) ------
__global__ __launch_bounds__(128) void k_enc(const float* __restrict__ enc) {
    __shared__ float sA[32 * HH];   // enc tile [32 n][128 h]
    int b = blockIdx.y;
    int n0 = blockIdx.x * 32;
    {
        const float4* src = (const float4*)(enc + ((size_t)b * NN + n0) * HH);
        float4* dst = (float4*)sA;
        for (int i = threadIdx.x; i < 32 * HH / 4; i += 128) dst[i] = src[i];
    }
    __syncthreads();

    int k = threadIdx.x;
    float acc[32];
#pragma unroll
    for (int n = 0; n < 32; n++) acc[n] = 0.f;

#pragma unroll 4
    for (int h = 0; h < HH; h++) {
        float w = g_W1T[h * HH + k];
#pragma unroll
        for (int n = 0; n < 32; n++)
            acc[n] = fmaf(sA[n * HH + h], w, acc[n]);
    }
    float* dst = g_te + ((size_t)b * HH + k) * NN + n0;
#pragma unroll
    for (int n = 0; n < 32; n++) dst[n] = tanhf(acc[n]);
}

// ------------------------- persistent per-batch decode -------------------------
__global__ __launch_bounds__(512) void k_decode(const float* __restrict__ enc,
                                                const float* __restrict__ b_ih,
                                                const float* __restrict__ b_hh,
                                                const float* __restrict__ v,
                                                float* __restrict__ out) {
    extern __shared__ float2 s_wc[];           // [SH * G4] weight cache (208 KB)
    __shared__ float2 s_dh[HH];                // {dec, hx}
    __shared__ float  s_cx[HH], s_td[HH], s_v[HH];
    __shared__ float  s_score[NN];
    __shared__ float  s_scr[4 * NN];           // multi-purpose scratch (8 KB)
    __shared__ unsigned char s_mask[NN];
    __shared__ float  s_rw[16];                // warp partials
    __shared__ int    s_ri[16];
    __shared__ float  s_rm[16];
    __shared__ int    s_sel;
    __shared__ float  s_smax;

    const int b = blockIdx.x;
    const int tid = threadIdx.x;
    const int lane = tid & 31, wid = tid >> 5;
    const float NEG_INF = __int_as_float(0xff800000);

    // one-time weight cache fill
    for (int i = tid; i < SH * G4; i += 512) s_wc[i] = g_Wc[i];

    if (tid < HH) { s_cx[tid] = 0.f; s_dh[tid].y = 0.f; s_v[tid] = v[tid]; }
    s_mask[tid] = 0;

    // dec0 = mean over n of encoder_outputs[b]
    {
        int h = tid & 127, q = tid >> 7;
        const float* p = enc + ((size_t)b * NN + (size_t)q * 128) * HH + h;
        float sum = 0.f;
        for (int n = 0; n < 128; n++) sum += p[(size_t)n * HH];
        s_scr[tid] = sum;
        __syncthreads();
        if (tid < HH)
            s_dh[tid].x = (s_scr[tid] + s_scr[tid + 128] + s_scr[tid + 256] + s_scr[tid + 384]) * (1.0f / NN);
    }
    __syncthreads();

    const float* teb = g_te + (size_t)b * HH * NN;
    const float bias = b_ih[tid] + b_hh[tid];   // j = tid (512 gate outputs)

    for (int t = 0; t < TT; t++) {
        // --- Phase 1: gates[j] = bias + dec . Wih[:,j] + hx . Whh[:,j] ---
        {
            float acc = bias;
#pragma unroll
            for (int hh = 0; hh < SH; hh++) {
                float2 w  = s_wc[hh * G4 + tid];
                float2 dh = s_dh[hh];
                acc = fmaf(dh.x, w.x, acc);
                acc = fmaf(dh.y, w.y, acc);
            }
#pragma unroll 8
            for (int hh = SH; hh < HH; hh++) {
                float2 w  = g_Wc[hh * G4 + tid];
                float2 dh = s_dh[hh];
                acc = fmaf(dh.x, w.x, acc);
                acc = fmaf(dh.y, w.y, acc);
            }
            s_scr[tid] = acc;
        }
        __syncthreads();

        // --- Phase 2: LSTM cell update (torch gate order i,f,g,o) ---
        if (tid < HH) {
            float gi = s_scr[tid];
            float gf = s_scr[HH + tid];
            float gg = s_scr[2 * HH + tid];
            float go = s_scr[3 * HH + tid];
            float si = fmaf(0.5f, tanhf(0.5f * gi), 0.5f);   // logistic
            float sf = fmaf(0.5f, tanhf(0.5f * gf), 0.5f);
            float tg = tanhf(gg);
            float so = fmaf(0.5f, tanhf(0.5f * go), 0.5f);
            float c  = fmaf(sf, s_cx[tid], si * tg);
            s_cx[tid] = c;
            s_dh[tid].y = so * tanhf(c);
        }
        __syncthreads();

        // --- Phase 3: td[k] = tanh(hx . W2T[:,k]) ---
        {
            int k = tid & 127, q = tid >> 7;
            float p = 0.f;
#pragma unroll
            for (int hh = q * 32; hh < q * 32 + 32; hh++)
                p = fmaf(s_dh[hh].y, g_W2T[hh * HH + k], p);
            s_scr[tid] = p;
        }
        __syncthreads();
        if (tid < HH)
            s_td[tid] = tanhf(s_scr[tid] + s_scr[tid + 128] + s_scr[tid + 256] + s_scr[tid + 384]);
        __syncthreads();

        // --- Phase 4a: partial score over k-quarter, float4 across n ---
        {
            int n4 = tid & 127, q = tid >> 7;
            const float4* tp = reinterpret_cast<const float4*>(teb + (size_t)(q * 32) * NN) + n4;
            float4 a = make_float4(0.f, 0.f, 0.f, 0.f);
#pragma unroll 8
            for (int kk = 0; kk < 32; kk++) {
                float4 te = tp[(size_t)kk * (NN / 4)];
                float td = s_td[q * 32 + kk];
                float vk = s_v[q * 32 + kk];
                a.x = fmaf(vk, __fdividef(te.x + td, fmaf(te.x, td, 1.f)), a.x);
                a.y = fmaf(vk, __fdividef(te.y + td, fmaf(te.y, td, 1.f)), a.y);
                a.z = fmaf(vk, __fdividef(te.z + td, fmaf(te.z, td, 1.f)), a.z);
                a.w = fmaf(vk, __fdividef(te.w + td, fmaf(te.w, td, 1.f)), a.w);
            }
            reinterpret_cast<float4*>(s_scr)[q * 128 + n4] = a;
        }
        __syncthreads();

        // --- Phase 4b: combine partials + gumbel + fused argmax/scoremax reduce ---
        {
            float sc = s_scr[tid] + s_scr[NN + tid] + s_scr[2 * NN + tid] + s_scr[3 * NN + tid];

            // gumbel noise (exact JAX threefry pipeline)
            unsigned sk0 = g_sub[2 * t], sk1 = g_sub[2 * t + 1];
            unsigned idx = (unsigned)(b * NN + tid);
            unsigned o0, o1;
            tf2x32(sk0, sk1, 0u, idx, o0, o1);
            unsigned bits = o0 ^ o1;
            float f   = __uint_as_float((bits >> 9) | 0x3f800000u) - 1.0f;
            float u   = fmaxf(1.17549435e-38f, f);
            float gum = -logf(-logf(u));

            float sm = s_mask[tid] ? NEG_INF : sc;
            s_score[tid] = sm;
            float mv = sm + gum;
            int   mi = tid;
            float sx = sm;
#pragma unroll
            for (int off = 16; off; off >>= 1) {
                float ov = __shfl_down_sync(0xffffffffu, mv, off);
                int   oi = __shfl_down_sync(0xffffffffu, mi, off);
                float os = __shfl_down_sync(0xffffffffu, sx, off);
                if (ov > mv || (ov == mv && oi < mi)) { mv = ov; mi = oi; }
                sx = fmaxf(sx, os);
            }
            if (lane == 0) { s_rw[wid] = mv; s_ri[wid] = mi; s_rm[wid] = sx; }
        }
        __syncthreads();
        if (wid == 0) {
            float mv = (lane < 16) ? s_rw[lane] : NEG_INF;
            int   mi = (lane < 16) ? s_ri[lane] : 0x7fffffff;
            float sx = (lane < 16) ? s_rm[lane] : NEG_INF;
#pragma unroll
            for (int off = 16; off; off >>= 1) {
                float ov = __shfl_down_sync(0xffffffffu, mv, off);
                int   oi = __shfl_down_sync(0xffffffffu, mi, off);
                float os = __shfl_down_sync(0xffffffffu, sx, off);
                if (ov > mv || (ov == mv && oi < mi)) { mv = ov; mi = oi; }
                sx = fmaxf(sx, os);
            }
            if (lane == 0) { s_sel = mi; s_smax = sx; }
        }
        __syncthreads();

        // --- softmax denominator ---
        {
            float e = expf(s_score[tid] - s_smax);   // exp(-inf) = 0 for masked
#pragma unroll
            for (int off = 16; off; off >>= 1)
                e += __shfl_down_sync(0xffffffffu, e, off);
            if (lane == 0) s_rw[wid] = e;
        }
        __syncthreads();

        if (tid == 0) {
            float tot = 0.f;
#pragma unroll
            for (int i = 0; i < 16; i++) tot += s_rw[i];
            int sel = s_sel;
            float prob = expf(s_score[sel] - s_smax) / tot;
            out[b * TT + t]           = (float)sel;
            out[BB * TT + b * TT + t] = logf(prob + 1e-9f);
            s_mask[sel] = 1;
        }
        __syncthreads();   // mask write + everyone done with s_dh before dec overwrite

        if (tid < HH)
            s_dh[tid].x = enc[((size_t)b * NN + s_sel) * HH + tid];
        __syncthreads();
    }
}

// ------------------------- launcher -------------------------
extern "C" void kernel_launch(void* const* d_in, const int* in_sizes, int n_in,
                              void* d_out, int out_size) {
    const float* enc  = (const float*)d_in[0];
    const float* W_ih = (const float*)d_in[1];
    const float* W_hh = (const float*)d_in[2];
    const float* b_ih = (const float*)d_in[3];
    const float* b_hh = (const float*)d_in[4];
    const float* W1   = (const float*)d_in[5];
    const float* W2   = (const float*)d_in[6];
    const float* v    = (const float*)d_in[7];
    (void)in_sizes; (void)n_in; (void)out_size;

    const int smem = SH * G4 * sizeof(float2);   // 212992 bytes
    cudaFuncSetAttribute(k_decode, cudaFuncAttributeMaxDynamicSharedMemorySize, smem);

    k_prep<<<64, 256>>>(W_ih, W_hh, W1, W2);
    k_enc<<<dim3(16, BB), 128>>>(enc);
    k_decode<<<BB, 512, smem>>>(enc, b_ih, b_hh, v, (float*)d_out);
}

// round 4
// speedup vs baseline: 2.2457x; 1.0005x over previous
#include <cuda_runtime.h>
#include <cuda_bf16.h>
#include <math.h>

// Problem constants (fixed shapes)
#define BB 128
#define NN 512
#define HH 128
#define TT 32
#define G4 512   // 4*H
#define SH 52    // weight hh-rows cached in smem (52*4KB = 208KB)

// ------------------------- device scratch (static; allocation-free) -------------------------
__device__ float  g_te[(size_t)BB * HH * NN];   // tanh(enc_trans): [b][k][n]  (33.5 MB)
__device__ float2 g_Wc[HH * G4];                // fused weights [hh][j] = {Wih[j][hh], Whh[j][hh]}
__device__ float  g_W2T[HH * HH];               // [hh][k]
__device__ float  g_W1T[HH * HH];               // [hh][k]
__device__ unsigned int g_sub[TT * 2];          // per-step categorical subkeys

// ------------------------- Threefry-2x32 (matches JAX partitionable mode) -------------------
__device__ __forceinline__ unsigned rotl32(unsigned x, int r) {
    return (x << r) | (x >> (32 - r));
}

__device__ __forceinline__ void tf2x32(unsigned k0, unsigned k1,
                                       unsigned x0, unsigned x1,
                                       unsigned& o0, unsigned& o1) {
    unsigned ks2 = k0 ^ k1 ^ 0x1BD11BDAu;
    x0 += k0; x1 += k1;
#define TF_RND(r) { x0 += x1; x1 = rotl32(x1, r); x1 ^= x0; }
    TF_RND(13) TF_RND(15) TF_RND(26) TF_RND(6)
    x0 += k1; x1 += ks2 + 1u;
    TF_RND(17) TF_RND(29) TF_RND(16) TF_RND(24)
    x0 += ks2; x1 += k0 + 2u;
    TF_RND(13) TF_RND(15) TF_RND(26) TF_RND(6)
    x0 += k0; x1 += k1 + 3u;
    TF_RND(17) TF_RND(29) TF_RND(16) TF_RND(24)
    x0 += k1; x1 += ks2 + 4u;
    TF_RND(13) TF_RND(15) TF_RND(26) TF_RND(6)
    x0 += ks2; x1 += k0 + 5u;
#undef TF_RND
    o0 = x0; o1 = x1;
}

// ------------------------- prep: weight layouts + subkey chain -------------------------
__global__ void k_prep(const float* __restrict__ W_ih, const float* __restrict__ W_hh,
                       const float* __restrict__ W1,   const float* __restrict__ W2) {
    int tid = blockIdx.x * blockDim.x + threadIdx.x;     // 64*256 = 16384 threads
    const int NT = 64 * 256;
    for (int i = tid; i < G4 * HH; i += NT) {
        int j = i / HH, hh = i % HH;
        g_Wc[hh * G4 + j] = make_float2(W_ih[i], W_hh[i]);
    }
    for (int i = tid; i < HH * HH; i += NT) {
        int k = i / HH, hh = i % HH;
        g_W2T[hh * HH + k] = W2[i];
        g_W1T[hh * HH + k] = W1[i];
    }
    if (tid == 0) {
        // key = jax.random.key(42) -> (0, 42); chain: key, sub = split(key)
        unsigned k0 = 0u, k1 = 42u;
        for (int t = 0; t < TT; t++) {
            unsigned a0, a1, b0, b1;
            tf2x32(k0, k1, 0u, 0u, a0, a1);   // new key
            tf2x32(k0, k1, 0u, 1u, b0, b1);   // sub key
            g_sub[2 * t] = b0; g_sub[2 * t + 1] = b1;
            k0 = a0; k1 = a1;
        }
    }
}

// ------------------------- enc_trans: g_te[b][k][n] = tanh(sum_h enc[b,n,h]*W1[k,h]) ------
__global__ __launch_bounds__(128) void k_enc(const float* __restrict__ enc) {
    __shared__ float sA[32 * HH];   // enc tile [32 n][128 h]
    int b = blockIdx.y;
    int n0 = blockIdx.x * 32;
    {
        const float4* src = (const float4*)(enc + ((size_t)b * NN + n0) * HH);
        float4* dst = (float4*)sA;
        for (int i = threadIdx.x; i < 32 * HH / 4; i += 128) dst[i] = src[i];
    }
    __syncthreads();

    int k = threadIdx.x;
    float acc[32];
#pragma unroll
    for (int n = 0; n < 32; n++) acc[n] = 0.f;

#pragma unroll 4
    for (int h = 0; h < HH; h++) {
        float w = g_W1T[h * HH + k];
#pragma unroll
        for (int n = 0; n < 32; n++)
            acc[n] = fmaf(sA[n * HH + h], w, acc[n]);
    }
    float* dst = g_te + ((size_t)b * HH + k) * NN + n0;
#pragma unroll
    for (int n = 0; n < 32; n++) dst[n] = tanhf(acc[n]);
}

// ------------------------- persistent per-batch decode -------------------------
__global__ __launch_bounds__(512) void k_decode(const float* __restrict__ enc,
                                                const float* __restrict__ b_ih,
                                                const float* __restrict__ b_hh,
                                                const float* __restrict__ v,
                                                float* __restrict__ out) {
    extern __shared__ float2 s_wc[];           // [SH * G4] weight cache (208 KB)
    __shared__ float2 s_dh[HH];                // {dec, hx}
    __shared__ float  s_cx[HH], s_td[HH], s_v[HH];
    __shared__ float  s_score[NN];
    __shared__ float  s_scr[4 * NN];           // multi-purpose scratch (8 KB)
    __shared__ unsigned char s_mask[NN];
    __shared__ float  s_rw[16];                // warp partials
    __shared__ int    s_ri[16];
    __shared__ float  s_rm[16];
    __shared__ int    s_sel;
    __shared__ float  s_smax;

    const int b = blockIdx.x;
    const int tid = threadIdx.x;
    const int lane = tid & 31, wid = tid >> 5;
    const float NEG_INF = __int_as_float(0xff800000);

    // one-time weight cache fill
    for (int i = tid; i < SH * G4; i += 512) s_wc[i] = g_Wc[i];

    if (tid < HH) { s_cx[tid] = 0.f; s_dh[tid].y = 0.f; s_v[tid] = v[tid]; }
    s_mask[tid] = 0;

    // dec0 = mean over n of encoder_outputs[b]
    {
        int h = tid & 127, q = tid >> 7;
        const float* p = enc + ((size_t)b * NN + (size_t)q * 128) * HH + h;
        float sum = 0.f;
        for (int n = 0; n < 128; n++) sum += p[(size_t)n * HH];
        s_scr[tid] = sum;
        __syncthreads();
        if (tid < HH)
            s_dh[tid].x = (s_scr[tid] + s_scr[tid + 128] + s_scr[tid + 256] + s_scr[tid + 384]) * (1.0f / NN);
    }
    __syncthreads();

    const float* teb = g_te + (size_t)b * HH * NN;
    const float bias = b_ih[tid] + b_hh[tid];   // j = tid (512 gate outputs)

    for (int t = 0; t < TT; t++) {
        // --- Phase 1: gates[j] = bias + dec . Wih[:,j] + hx . Whh[:,j] ---
        {
            float acc = bias;
#pragma unroll
            for (int hh = 0; hh < SH; hh++) {
                float2 w  = s_wc[hh * G4 + tid];
                float2 dh = s_dh[hh];
                acc = fmaf(dh.x, w.x, acc);
                acc = fmaf(dh.y, w.y, acc);
            }
#pragma unroll 8
            for (int hh = SH; hh < HH; hh++) {
                float2 w  = g_Wc[hh * G4 + tid];
                float2 dh = s_dh[hh];
                acc = fmaf(dh.x, w.x, acc);
                acc = fmaf(dh.y, w.y, acc);
            }
            s_scr[tid] = acc;
        }
        __syncthreads();

        // --- Phase 2: LSTM cell update (torch gate order i,f,g,o) ---
        if (tid < HH) {
            float gi = s_scr[tid];
            float gf = s_scr[HH + tid];
            float gg = s_scr[2 * HH + tid];
            float go = s_scr[3 * HH + tid];
            float si = fmaf(0.5f, tanhf(0.5f * gi), 0.5f);   // logistic
            float sf = fmaf(0.5f, tanhf(0.5f * gf), 0.5f);
            float tg = tanhf(gg);
            float so = fmaf(0.5f, tanhf(0.5f * go), 0.5f);
            float c  = fmaf(sf, s_cx[tid], si * tg);
            s_cx[tid] = c;
            s_dh[tid].y = so * tanhf(c);
        }
        __syncthreads();

        // --- Phase 3: td[k] = tanh(hx . W2T[:,k]) ---
        {
            int k = tid & 127, q = tid >> 7;
            float p = 0.f;
#pragma unroll
            for (int hh = q * 32; hh < q * 32 + 32; hh++)
                p = fmaf(s_dh[hh].y, g_W2T[hh * HH + k], p);
            s_scr[tid] = p;
        }
        __syncthreads();
        if (tid < HH)
            s_td[tid] = tanhf(s_scr[tid] + s_scr[tid + 128] + s_scr[tid + 256] + s_scr[tid + 384]);
        __syncthreads();

        // --- Phase 4a: partial score over k-quarter, float4 across n ---
        {
            int n4 = tid & 127, q = tid >> 7;
            const float4* tp = reinterpret_cast<const float4*>(teb + (size_t)(q * 32) * NN) + n4;
            float4 a = make_float4(0.f, 0.f, 0.f, 0.f);
#pragma unroll 8
            for (int kk = 0; kk < 32; kk++) {
                float4 te = tp[(size_t)kk * (NN / 4)];
                float td = s_td[q * 32 + kk];
                float vk = s_v[q * 32 + kk];
                a.x = fmaf(vk, __fdividef(te.x + td, fmaf(te.x, td, 1.f)), a.x);
                a.y = fmaf(vk, __fdividef(te.y + td, fmaf(te.y, td, 1.f)), a.y);
                a.z = fmaf(vk, __fdividef(te.z + td, fmaf(te.z, td, 1.f)), a.z);
                a.w = fmaf(vk, __fdividef(te.w + td, fmaf(te.w, td, 1.f)), a.w);
            }
            reinterpret_cast<float4*>(s_scr)[q * 128 + n4] = a;
        }
        __syncthreads();

        // --- Phase 4b: combine partials + gumbel + fused argmax/scoremax reduce ---
        {
            float sc = s_scr[tid] + s_scr[NN + tid] + s_scr[2 * NN + tid] + s_scr[3 * NN + tid];

            // gumbel noise (exact JAX threefry pipeline)
            unsigned sk0 = g_sub[2 * t], sk1 = g_sub[2 * t + 1];
            unsigned idx = (unsigned)(b * NN + tid);
            unsigned o0, o1;
            tf2x32(sk0, sk1, 0u, idx, o0, o1);
            unsigned bits = o0 ^ o1;
            float f   = __uint_as_float((bits >> 9) | 0x3f800000u) - 1.0f;
            float u   = fmaxf(1.17549435e-38f, f);
            float gum = -logf(-logf(u));

            float sm = s_mask[tid] ? NEG_INF : sc;
            s_score[tid] = sm;
            float mv = sm + gum;
            int   mi = tid;
            float sx = sm;
#pragma unroll
            for (int off = 16; off; off >>= 1) {
                float ov = __shfl_down_sync(0xffffffffu, mv, off);
                int   oi = __shfl_down_sync(0xffffffffu, mi, off);
                float os = __shfl_down_sync(0xffffffffu, sx, off);
                if (ov > mv || (ov == mv && oi < mi)) { mv = ov; mi = oi; }
                sx = fmaxf(sx, os);
            }
            if (lane == 0) { s_rw[wid] = mv; s_ri[wid] = mi; s_rm[wid] = sx; }
        }
        __syncthreads();
        if (wid == 0) {
            float mv = (lane < 16) ? s_rw[lane] : NEG_INF;
            int   mi = (lane < 16) ? s_ri[lane] : 0x7fffffff;
            float sx = (lane < 16) ? s_rm[lane] : NEG_INF;
#pragma unroll
            for (int off = 16; off; off >>= 1) {
                float ov = __shfl_down_sync(0xffffffffu, mv, off);
                int   oi = __shfl_down_sync(0xffffffffu, mi, off);
                float os = __shfl_down_sync(0xffffffffu, sx, off);
                if (ov > mv || (ov == mv && oi < mi)) { mv = ov; mi = oi; }
                sx = fmaxf(sx, os);
            }
            if (lane == 0) { s_sel = mi; s_smax = sx; }
        }
        __syncthreads();

        // --- softmax denominator ---
        {
            float e = expf(s_score[tid] - s_smax);   // exp(-inf) = 0 for masked
#pragma unroll
            for (int off = 16; off; off >>= 1)
                e += __shfl_down_sync(0xffffffffu, e, off);
            if (lane == 0) s_rw[wid] = e;
        }
        __syncthreads();

        if (tid == 0) {
            float tot = 0.f;
#pragma unroll
            for (int i = 0; i < 16; i++) tot += s_rw[i];
            int sel = s_sel;
            float prob = expf(s_score[sel] - s_smax) / tot;
            out[b * TT + t]           = (float)sel;
            out[BB * TT + b * TT + t] = logf(prob + 1e-9f);
            s_mask[sel] = 1;
        }
        __syncthreads();   // mask write + everyone done with s_dh before dec overwrite

        if (tid < HH)
            s_dh[tid].x = enc[((size_t)b * NN + s_sel) * HH + tid];
        __syncthreads();
    }
}

// ------------------------- launcher -------------------------
extern "C" void kernel_launch(void* const* d_in, const int* in_sizes, int n_in,
                              void* d_out, int out_size) {
    const float* enc  = (const float*)d_in[0];
    const float* W_ih = (const float*)d_in[1];
    const float* W_hh = (const float*)d_in[2];
    const float* b_ih = (const float*)d_in[3];
    const float* b_hh = (const float*)d_in[4];
    const float* W1   = (const float*)d_in[5];
    const float* W2   = (const float*)d_in[6];
    const float* v    = (const float*)d_in[7];
    (void)in_sizes; (void)n_in; (void)out_size;

    const int smem = SH * G4 * sizeof(float2);   // 212992 bytes
    cudaFuncSetAttribute(k_decode, cudaFuncAttributeMaxDynamicSharedMemorySize, smem);

    k_prep<<<64, 256>>>(W_ih, W_hh, W1, W2);
    k_enc<<<dim3(16, BB), 128>>>(enc);
    k_decode<<<BB, 512, smem>>>(enc, b_ih, b_hh, v, (float*)d_out);
}